// round 5
// baseline (speedup 1.0000x reference)
#include <cuda_runtime.h>
#include <cstdint>
#include <math.h>

#define BATCH 2
#define TSEQ  2048
#define DMODEL 1024
#define NHEAD 16
#define DHEAD 64
#define BT (BATCH * TSEQ)          // 4096
#define QKV_N (3 * DMODEL)         // 3072
#define KDIM DMODEL                // K = 1024 for both GEMMs

// ---------------- scratch (device globals; allocation-free rule) ----------
__device__ __align__(256) float g_qkv[(size_t)BT * QKV_N];       // [4096,3072]
__device__ __align__(256) float g_attn[(size_t)BT * DMODEL];     // [4096,1024]
__device__ __align__(256) float g_xr[(size_t)BT * DMODEL];       // x, tf32-rounded
__device__ __align__(256) float g_wt_attn[(size_t)QKV_N * KDIM]; // W_attn^T [3072,1024]
__device__ __align__(256) float g_wt_proj[(size_t)DMODEL * KDIM];// W_proj^T [1024,1024]

// ---------------- helpers ---------------------------------------------------
__device__ __forceinline__ uint32_t smem_u32(const void* p) {
    uint32_t a;
    asm("{ .reg .u64 t; cvta.to.shared.u64 t, %1; cvt.u32.u64 %0, t; }" : "=r"(a) : "l"(p));
    return a;
}
__device__ __forceinline__ float rna_tf32(float x) {
    float r;
    asm("cvt.rna.tf32.f32 %0, %1;" : "=f"(r) : "f"(x));
    return r;
}
__device__ __forceinline__ float ex2f(float x) {
    float r;
    asm("ex2.approx.f32 %0, %1;" : "=f"(r) : "f"(x));
    return r;
}
__device__ __forceinline__ void cp_async16(uint32_t saddr, const void* gptr) {
    asm volatile("cp.async.cg.shared.global [%0], [%1], 16;" :: "r"(saddr), "l"(gptr));
}
__device__ __forceinline__ void mma_tf32_16n8k8(float* d, const uint32_t* a, const uint32_t* b) {
    asm volatile(
        "mma.sync.aligned.m16n8k8.row.col.f32.tf32.tf32.f32 "
        "{%0,%1,%2,%3}, {%4,%5,%6,%7}, {%8,%9}, {%0,%1,%2,%3};"
        : "+f"(d[0]), "+f"(d[1]), "+f"(d[2]), "+f"(d[3])
        : "r"(a[0]), "r"(a[1]), "r"(a[2]), "r"(a[3]), "r"(b[0]), "r"(b[1]));
}

// ---------------- prep kernels ---------------------------------------------
__global__ void round_tf32_kernel(const float4* __restrict__ src,
                                  float4* __restrict__ dst, int n4) {
    int i = blockIdx.x * blockDim.x + threadIdx.x;
    if (i < n4) {
        float4 v = src[i];
        v.x = rna_tf32(v.x); v.y = rna_tf32(v.y);
        v.z = rna_tf32(v.z); v.w = rna_tf32(v.w);
        dst[i] = v;
    }
}

// Wt[n][k] = rna(W[k][n]);  W is [K, N] row-major
__global__ void transpose_rna_kernel(const float* __restrict__ W,
                                     float* __restrict__ Wt, int K, int N) {
    __shared__ float tile[32][33];
    int nx = blockIdx.x * 32, kx = blockIdx.y * 32;
    for (int i = threadIdx.y; i < 32; i += 8)
        tile[i][threadIdx.x] = W[(size_t)(kx + i) * N + nx + threadIdx.x];
    __syncthreads();
    for (int i = threadIdx.y; i < 32; i += 8)
        Wt[(size_t)(nx + i) * K + kx + threadIdx.x] = rna_tf32(tile[threadIdx.x][i]);
}

// ---------------- tf32 mma.sync GEMM ---------------------------------------
// ROUND_OUT: RNA-round the output (when it feeds another tf32 mma consumer).
#define GSTRIDE 36
#define GBUF (128 * GSTRIDE)
#define GEMM_SMEM (2 * 2 * GBUF * 4)

template <bool ROUND_OUT>
__global__ __launch_bounds__(256, 2) void gemm_tf32_mma(
    const float* __restrict__ A, const float* __restrict__ Bt,
    const float* __restrict__ bias, float* __restrict__ C, int N)
{
    extern __shared__ float sm[];
    float* As = sm;
    float* Bs = sm + 2 * GBUF;

    const int tid = threadIdx.x, wid = tid >> 5, lid = tid & 31;
    const int m0 = blockIdx.y * 128, n0 = blockIdx.x * 128;
    const int m_warp = (wid >> 2) * 64;
    const int n_warp = (wid & 3) * 32;

    const uint32_t sA = smem_u32(As), sB = smem_u32(Bs);

    float acc[4][4][4];
#pragma unroll
    for (int i = 0; i < 4; i++)
#pragma unroll
        for (int j = 0; j < 4; j++)
#pragma unroll
            for (int q = 0; q < 4; q++) acc[i][j][q] = 0.f;

    auto load_stage = [&](int c, int buf) {
        const int k0 = c * 32;
#pragma unroll
        for (int i = 0; i < 4; i++) {
            int ch = tid + i * 256;
            int row = ch >> 3, c16 = ch & 7;
            uint32_t so = (uint32_t)((buf * GBUF + row * GSTRIDE + c16 * 4) * 4);
            cp_async16(sA + so, A + (size_t)(m0 + row) * KDIM + k0 + c16 * 4);
            cp_async16(sB + so, Bt + (size_t)(n0 + row) * KDIM + k0 + c16 * 4);
        }
        asm volatile("cp.async.commit_group;" ::: "memory");
    };

    load_stage(0, 0);

    const int NCHUNK = KDIM / 32;
    for (int c = 0; c < NCHUNK; c++) {
        if (c + 1 < NCHUNK) {
            load_stage(c + 1, (c + 1) & 1);
            asm volatile("cp.async.wait_group 1;" ::: "memory");
        } else {
            asm volatile("cp.async.wait_group 0;" ::: "memory");
        }
        __syncthreads();

        const float* Ab = As + (c & 1) * GBUF;
        const float* Bb = Bs + (c & 1) * GBUF;
#pragma unroll
        for (int ks = 0; ks < 4; ks++) {
            const int k_lo = ks * 8 + (lid & 3);
            uint32_t af[4][4], bf[4][2];
#pragma unroll
            for (int mt = 0; mt < 4; mt++) {
                int r0 = m_warp + mt * 16 + (lid >> 2);
                af[mt][0] = __float_as_uint(Ab[r0 * GSTRIDE + k_lo]);
                af[mt][1] = __float_as_uint(Ab[(r0 + 8) * GSTRIDE + k_lo]);
                af[mt][2] = __float_as_uint(Ab[r0 * GSTRIDE + k_lo + 4]);
                af[mt][3] = __float_as_uint(Ab[(r0 + 8) * GSTRIDE + k_lo + 4]);
            }
#pragma unroll
            for (int nt = 0; nt < 4; nt++) {
                int nc = n_warp + nt * 8 + (lid >> 2);
                bf[nt][0] = __float_as_uint(Bb[nc * GSTRIDE + k_lo]);
                bf[nt][1] = __float_as_uint(Bb[nc * GSTRIDE + k_lo + 4]);
            }
#pragma unroll
            for (int mt = 0; mt < 4; mt++)
#pragma unroll
                for (int nt = 0; nt < 4; nt++)
                    mma_tf32_16n8k8(acc[mt][nt], af[mt], bf[nt]);
        }
        __syncthreads();
    }

#pragma unroll
    for (int mt = 0; mt < 4; mt++) {
        int r0 = m0 + m_warp + mt * 16 + (lid >> 2);
#pragma unroll
        for (int nt = 0; nt < 4; nt++) {
            int cb = n0 + n_warp + nt * 8 + 2 * (lid & 3);
            float2 bz = *(const float2*)(bias + cb);
            float2 o0, o1;
            o0.x = acc[mt][nt][0] + bz.x; o0.y = acc[mt][nt][1] + bz.y;
            o1.x = acc[mt][nt][2] + bz.x; o1.y = acc[mt][nt][3] + bz.y;
            if (ROUND_OUT) {
                o0.x = rna_tf32(o0.x); o0.y = rna_tf32(o0.y);
                o1.x = rna_tf32(o1.x); o1.y = rna_tf32(o1.y);
            }
            *(float2*)(C + (size_t)r0 * N + cb) = o0;
            *(float2*)(C + (size_t)(r0 + 8) * N + cb) = o1;
        }
    }
}

// ---------------- tf32 mma flash attention (2-stage pipelined K/V) ---------
// CTA: 128 queries, 4 warps. K/V in 64-key double-buffered subtiles.
// smem stride 68: (4r+c)%32 bank permutation, conflict-free fragment LDS.
#define ATPAD 68
#define QTILE_F (128 * ATPAD)
#define SUBT_F  (64 * ATPAD)
#define ATT_SMEM ((QTILE_F + 4 * SUBT_F) * 4)   // 104448 bytes

__global__ __launch_bounds__(128, 2) void attn_mma_kernel(
    const float* __restrict__ qkv, float* __restrict__ out)
{
    extern __shared__ float sm[];
    float* Qs  = sm;                       // [128][ATPAD]
    float* Kb0 = sm + QTILE_F;             // [2][64][ATPAD]
    float* Vb0 = sm + QTILE_F + 2 * SUBT_F;// [2][64][ATPAD]

    const int tid = threadIdx.x, wid = tid >> 5, lid = tid & 31;
    const int cq = lid & 3, rq = lid >> 2;
    const int b = blockIdx.z, h = blockIdx.y;
    const int bx = (int)gridDim.x - 1 - (int)blockIdx.x;   // heavy blocks first
    const int q0 = bx * 128;
    const float* base = qkv + (size_t)b * TSEQ * QKV_N + h * DHEAD;

    const uint32_t sQ = smem_u32(Qs), sKb = smem_u32(Kb0), sVb = smem_u32(Vb0);

    // Q tile: 128 rows x 16 float4 chunks
#pragma unroll
    for (int i = 0; i < 16; i++) {
        int ch = tid + i * 128;
        int r = ch >> 4, c4 = ch & 15;
        cp_async16(sQ + (uint32_t)(r * ATPAD + c4 * 4) * 4,
                   base + (size_t)(q0 + r) * QKV_N + c4 * 4);
    }
    asm volatile("cp.async.commit_group;" ::: "memory");

    auto load_sub = [&](int st) {
        const int buf = st & 1;
#pragma unroll
        for (int i = 0; i < 8; i++) {
            int ch = tid + i * 128;
            int r = ch >> 4, c4 = ch & 15;
            const float* g = base + (size_t)(st * 64 + r) * QKV_N + c4 * 4;
            uint32_t so = (uint32_t)(buf * SUBT_F + r * ATPAD + c4 * 4) * 4;
            cp_async16(sKb + so, g + DMODEL);
            cp_async16(sVb + so, g + 2 * DMODEL);
        }
        asm volatile("cp.async.commit_group;" ::: "memory");
    };

    float acc[2][8][4];
#pragma unroll
    for (int mt = 0; mt < 2; mt++)
#pragma unroll
        for (int nt = 0; nt < 8; nt++)
#pragma unroll
            for (int j = 0; j < 4; j++) acc[mt][nt][j] = 0.f;
    float mrow[2][2], lrow[2][2];
#pragma unroll
    for (int mt = 0; mt < 2; mt++) {
        mrow[mt][0] = -1e30f; mrow[mt][1] = -1e30f;
        lrow[mt][0] = 0.f;    lrow[mt][1] = 0.f;
    }

    const int mrow0 = wid * 32;
    const float SC = 0.1803368801111f;   // (1/8) * log2(e)

    load_sub(0);

    const int nst = 2 * bx + 2;
#pragma unroll 1
    for (int st = 0; st < nst; st++) {
        if (st + 1 < nst) {
            load_sub(st + 1);
            asm volatile("cp.async.wait_group 1;" ::: "memory");
        } else {
            asm volatile("cp.async.wait_group 0;" ::: "memory");
        }
        __syncthreads();

        const float* Kbuf = Kb0 + (st & 1) * SUBT_F;
        const float* Vbuf = Vb0 + (st & 1) * SUBT_F;

        // ---- S = Q @ K^T ----
        float s[2][8][4];
#pragma unroll
        for (int mt = 0; mt < 2; mt++)
#pragma unroll
            for (int nt = 0; nt < 8; nt++)
#pragma unroll
                for (int j = 0; j < 4; j++) s[mt][nt][j] = 0.f;

#pragma unroll
        for (int ks = 0; ks < 8; ks++) {
            uint32_t af[2][4];
#pragma unroll
            for (int mt = 0; mt < 2; mt++) {
                const float* qb = Qs + (mrow0 + mt * 16 + rq) * ATPAD + ks * 8 + cq;
                af[mt][0] = __float_as_uint(qb[0]);
                af[mt][1] = __float_as_uint(qb[8 * ATPAD]);
                af[mt][2] = __float_as_uint(qb[4]);
                af[mt][3] = __float_as_uint(qb[8 * ATPAD + 4]);
            }
#pragma unroll
            for (int nt = 0; nt < 8; nt++) {
                uint32_t bf[2];
                const float* kp = Kbuf + (nt * 8 + rq) * ATPAD + ks * 8 + cq;
                bf[0] = __float_as_uint(kp[0]);
                bf[1] = __float_as_uint(kp[4]);
                mma_tf32_16n8k8(s[0][nt], af[0], bf);
                mma_tf32_16n8k8(s[1][nt], af[1], bf);
            }
        }

        // ---- scale, causal mask, online softmax (base-2) ----
        const bool diag = (st >= 2 * bx);
#pragma unroll
        for (int mt = 0; mt < 2; mt++) {
#pragma unroll
            for (int nt = 0; nt < 8; nt++)
#pragma unroll
                for (int j = 0; j < 4; j++) s[mt][nt][j] *= SC;

            if (diag) {
                int row0 = q0 + mrow0 + mt * 16 + rq;
#pragma unroll
                for (int nt = 0; nt < 8; nt++) {
                    int c0 = st * 64 + nt * 8 + 2 * cq;
                    if (c0     > row0)     s[mt][nt][0] = -1e30f;
                    if (c0 + 1 > row0)     s[mt][nt][1] = -1e30f;
                    if (c0     > row0 + 8) s[mt][nt][2] = -1e30f;
                    if (c0 + 1 > row0 + 8) s[mt][nt][3] = -1e30f;
                }
            }

            float mx0 = -1e30f, mx1 = -1e30f;
#pragma unroll
            for (int nt = 0; nt < 8; nt++) {
                mx0 = fmaxf(mx0, fmaxf(s[mt][nt][0], s[mt][nt][1]));
                mx1 = fmaxf(mx1, fmaxf(s[mt][nt][2], s[mt][nt][3]));
            }
            mx0 = fmaxf(mx0, __shfl_xor_sync(0xffffffffu, mx0, 1));
            mx0 = fmaxf(mx0, __shfl_xor_sync(0xffffffffu, mx0, 2));
            mx1 = fmaxf(mx1, __shfl_xor_sync(0xffffffffu, mx1, 1));
            mx1 = fmaxf(mx1, __shfl_xor_sync(0xffffffffu, mx1, 2));

            float mn0 = fmaxf(mrow[mt][0], mx0);
            float mn1 = fmaxf(mrow[mt][1], mx1);
            float sc0 = ex2f(mrow[mt][0] - mn0);
            float sc1 = ex2f(mrow[mt][1] - mn1);
            mrow[mt][0] = mn0; mrow[mt][1] = mn1;
            lrow[mt][0] *= sc0; lrow[mt][1] *= sc1;
#pragma unroll
            for (int nt = 0; nt < 8; nt++) {
                acc[mt][nt][0] *= sc0; acc[mt][nt][1] *= sc0;
                acc[mt][nt][2] *= sc1; acc[mt][nt][3] *= sc1;
            }
            float su0 = 0.f, su1 = 0.f;
#pragma unroll
            for (int nt = 0; nt < 8; nt++) {
                s[mt][nt][0] = rna_tf32(ex2f(s[mt][nt][0] - mn0)); su0 += s[mt][nt][0];
                s[mt][nt][1] = rna_tf32(ex2f(s[mt][nt][1] - mn0)); su0 += s[mt][nt][1];
                s[mt][nt][2] = rna_tf32(ex2f(s[mt][nt][2] - mn1)); su1 += s[mt][nt][2];
                s[mt][nt][3] = rna_tf32(ex2f(s[mt][nt][3] - mn1)); su1 += s[mt][nt][3];
            }
            su0 += __shfl_xor_sync(0xffffffffu, su0, 1);
            su0 += __shfl_xor_sync(0xffffffffu, su0, 2);
            su1 += __shfl_xor_sync(0xffffffffu, su1, 1);
            su1 += __shfl_xor_sync(0xffffffffu, su1, 2);
            lrow[mt][0] += su0; lrow[mt][1] += su1;
        }

        // ---- O += P @ V ----
        const int src  = (lid & 28) | ((lid >> 1) & 1);
        const int src2 = src + 2;
#pragma unroll
        for (int k8 = 0; k8 < 8; k8++) {
            uint32_t pa[2][4];
#pragma unroll
            for (int mt = 0; mt < 2; mt++) {
                float v0 = __shfl_sync(0xffffffffu, s[mt][k8][0], src);
                float v1 = __shfl_sync(0xffffffffu, s[mt][k8][1], src);
                float w0 = __shfl_sync(0xffffffffu, s[mt][k8][0], src2);
                float w1 = __shfl_sync(0xffffffffu, s[mt][k8][1], src2);
                float x0 = __shfl_sync(0xffffffffu, s[mt][k8][2], src);
                float x1 = __shfl_sync(0xffffffffu, s[mt][k8][3], src);
                float y0 = __shfl_sync(0xffffffffu, s[mt][k8][2], src2);
                float y1 = __shfl_sync(0xffffffffu, s[mt][k8][3], src2);
                bool e = (lid & 1) != 0;
                pa[mt][0] = __float_as_uint(e ? v1 : v0);
                pa[mt][2] = __float_as_uint(e ? w1 : w0);
                pa[mt][1] = __float_as_uint(e ? x1 : x0);
                pa[mt][3] = __float_as_uint(e ? y1 : y0);
            }
#pragma unroll
            for (int nt = 0; nt < 8; nt++) {
                uint32_t bf[2];
                const float* vb = Vbuf + (k8 * 8 + cq) * ATPAD + nt * 8 + rq;
                bf[0] = __float_as_uint(vb[0]);
                bf[1] = __float_as_uint(vb[4 * ATPAD]);
                mma_tf32_16n8k8(acc[0][nt], pa[0], bf);
                mma_tf32_16n8k8(acc[1][nt], pa[1], bf);
            }
        }
        __syncthreads();   // buffer free for the next prefetch
    }

    // ---- epilogue: normalize, tf32-round (feeds proj GEMM), store ----
    float* outp = out + (size_t)b * TSEQ * DMODEL + h * DHEAD;
#pragma unroll
    for (int mt = 0; mt < 2; mt++) {
        float i0 = 1.f / lrow[mt][0], i1 = 1.f / lrow[mt][1];
        int row0 = q0 + mrow0 + mt * 16 + rq;
#pragma unroll
        for (int nt = 0; nt < 8; nt++) {
            int col = nt * 8 + 2 * cq;
            float2 o0, o1;
            o0.x = rna_tf32(acc[mt][nt][0] * i0);
            o0.y = rna_tf32(acc[mt][nt][1] * i0);
            o1.x = rna_tf32(acc[mt][nt][2] * i1);
            o1.y = rna_tf32(acc[mt][nt][3] * i1);
            *(float2*)(outp + (size_t)row0 * DMODEL + col) = o0;
            *(float2*)(outp + (size_t)(row0 + 8) * DMODEL + col) = o1;
        }
    }
}

// ---------------------------------------------------------------------------
extern "C" void kernel_launch(void* const* d_in, const int* in_sizes, int n_in,
                              void* d_out, int out_size)
{
    const float* x      = (const float*)d_in[0];   // [2,2048,1024]
    const float* W_attn = (const float*)d_in[1];   // [1024,3072]
    const float* b_attn = (const float*)d_in[2];   // [3072]
    const float* W_proj = (const float*)d_in[3];   // [1024,1024]
    const float* b_proj = (const float*)d_in[4];   // [1024]
    float* out = (float*)d_out;                    // [2,2048,1024]

    float *qkv, *attn, *xr, *wta, *wtp;
    cudaGetSymbolAddress((void**)&qkv,  g_qkv);
    cudaGetSymbolAddress((void**)&attn, g_attn);
    cudaGetSymbolAddress((void**)&xr,   g_xr);
    cudaGetSymbolAddress((void**)&wta,  g_wt_attn);
    cudaGetSymbolAddress((void**)&wtp,  g_wt_proj);

    cudaFuncSetAttribute(gemm_tf32_mma<true>,
                         cudaFuncAttributeMaxDynamicSharedMemorySize, GEMM_SMEM);
    cudaFuncSetAttribute(gemm_tf32_mma<false>,
                         cudaFuncAttributeMaxDynamicSharedMemorySize, GEMM_SMEM);
    cudaFuncSetAttribute(attn_mma_kernel,
                         cudaFuncAttributeMaxDynamicSharedMemorySize, ATT_SMEM);

    // prep: tf32-round x; transpose+round weights
    {
        int n4 = BT * DMODEL / 4;
        round_tf32_kernel<<<(n4 + 255) / 256, 256>>>((const float4*)x, (float4*)xr, n4);
        transpose_rna_kernel<<<dim3(QKV_N / 32, KDIM / 32), dim3(32, 8)>>>(W_attn, wta, KDIM, QKV_N);
        transpose_rna_kernel<<<dim3(DMODEL / 32, KDIM / 32), dim3(32, 8)>>>(W_proj, wtp, KDIM, DMODEL);
    }
    // 1) QKV projection (tf32 mma.sync; output RNA-rounded for attention)
    gemm_tf32_mma<true><<<dim3(QKV_N / 128, BT / 128), 256, GEMM_SMEM>>>(xr, wta, b_attn, qkv, QKV_N);
    // 2) causal attention (tf32 mma.sync flash attention, pipelined)
    {
        dim3 grid(TSEQ / 128, NHEAD, BATCH);
        attn_mma_kernel<<<grid, 128, ATT_SMEM>>>(qkv, attn);
    }
    // 3) output projection (tf32 mma.sync; final output stays fp32)
    gemm_tf32_mma<false><<<dim3(DMODEL / 128, BT / 128), 256, GEMM_SMEM>>>(attn, wtp, b_proj, out, DMODEL);
}

// round 6
// speedup vs baseline: 1.7918x; 1.7918x over previous
#include <cuda_runtime.h>
#include <cuda_fp16.h>
#include <cstdint>
#include <math.h>

#define BATCH 2
#define TSEQ  2048
#define DMODEL 1024
#define NHEAD 16
#define DHEAD 64
#define BT (BATCH * TSEQ)          // 4096
#define QKV_N (3 * DMODEL)         // 3072
#define KDIM DMODEL                // K = 1024 for both GEMMs

// ---------------- scratch (device globals; allocation-free rule) ----------
__device__ __align__(256) __half g_qkvh[(size_t)BT * QKV_N];      // [4096,3072]
__device__ __align__(256) __half g_attnh[(size_t)BT * DMODEL];    // [4096,1024]
__device__ __align__(256) __half g_xh[(size_t)BT * DMODEL];       // x in fp16
__device__ __align__(256) __half g_wt_attn[(size_t)QKV_N * KDIM]; // W_attn^T fp16
__device__ __align__(256) __half g_wt_proj[(size_t)DMODEL * KDIM];// W_proj^T fp16

// ---------------- helpers ---------------------------------------------------
__device__ __forceinline__ uint32_t smem_u32(const void* p) {
    uint32_t a;
    asm("{ .reg .u64 t; cvta.to.shared.u64 t, %1; cvt.u32.u64 %0, t; }" : "=r"(a) : "l"(p));
    return a;
}
__device__ __forceinline__ float ex2f(float x) {
    float r;
    asm("ex2.approx.f32 %0, %1;" : "=f"(r) : "f"(x));
    return r;
}
__device__ __forceinline__ void cp_async16(uint32_t saddr, const void* gptr) {
    asm volatile("cp.async.cg.shared.global [%0], [%1], 16;" :: "r"(saddr), "l"(gptr));
}
__device__ __forceinline__ void mma_f16(float* d, const uint32_t* a, const uint32_t* b) {
    asm volatile(
        "mma.sync.aligned.m16n8k16.row.col.f32.f16.f16.f32 "
        "{%0,%1,%2,%3}, {%4,%5,%6,%7}, {%8,%9}, {%0,%1,%2,%3};"
        : "+f"(d[0]), "+f"(d[1]), "+f"(d[2]), "+f"(d[3])
        : "r"(a[0]), "r"(a[1]), "r"(a[2]), "r"(a[3]), "r"(b[0]), "r"(b[1]));
}
#define LDSM4(R0,R1,R2,R3,ADDR) \
  asm volatile("ldmatrix.sync.aligned.m8n8.x4.shared.b16 {%0,%1,%2,%3}, [%4];" \
    : "=r"(R0),"=r"(R1),"=r"(R2),"=r"(R3) : "r"(ADDR))
#define LDSM4T(R0,R1,R2,R3,ADDR) \
  asm volatile("ldmatrix.sync.aligned.m8n8.x4.trans.shared.b16 {%0,%1,%2,%3}, [%4];" \
    : "=r"(R0),"=r"(R1),"=r"(R2),"=r"(R3) : "r"(ADDR))
__device__ __forceinline__ uint32_t packh2(float a, float b) {
    __half2 h = __floats2half2_rn(a, b);
    return *(uint32_t*)&h;
}

// ---------------- prep kernels ---------------------------------------------
__global__ void f2h_kernel(const float4* __restrict__ src,
                           uint2* __restrict__ dst, int n4) {
    int i = blockIdx.x * blockDim.x + threadIdx.x;
    if (i < n4) {
        float4 v = src[i];
        uint2 o;
        o.x = packh2(v.x, v.y);
        o.y = packh2(v.z, v.w);
        dst[i] = o;
    }
}

// Wt[n][k] = half(W[k][n]);  W is [K, N] row-major fp32
__global__ void transpose_f2h_kernel(const float* __restrict__ W,
                                     __half* __restrict__ Wt, int K, int N) {
    __shared__ float tile[32][33];
    int nx = blockIdx.x * 32, kx = blockIdx.y * 32;
    for (int i = threadIdx.y; i < 32; i += 8)
        tile[i][threadIdx.x] = W[(size_t)(kx + i) * N + nx + threadIdx.x];
    __syncthreads();
    for (int i = threadIdx.y; i < 32; i += 8)
        Wt[(size_t)(nx + i) * K + kx + threadIdx.x] = __float2half_rn(tile[threadIdx.x][i]);
}

// ---------------- fp16 mma.sync GEMM ---------------------------------------
// C[M,N] = A[M,K]h @ Bt[N,K]h^T + bias[N].  CTA 128x128, BK=64, 3 stages.
// smem halfs, stride 72: bank (4r+c)%32 permutation, conflict-free LDS.
#define HSTR 72
#define ABUF (128 * HSTR)                 // halfs per stage per matrix
#define GEMM_SMEM (6 * ABUF * 2)          // 110592 bytes
#define NCH 16                            // 1024 / 64

template <bool HALF_OUT>
__global__ __launch_bounds__(256, 2) void gemm_f16_mma(
    const __half* __restrict__ A, const __half* __restrict__ Bt,
    const float* __restrict__ bias, void* __restrict__ Cv, int N)
{
    extern __shared__ __half smh[];
    __half* As = smh;                 // [3][128][HSTR]
    __half* Bs = smh + 3 * ABUF;      // [3][128][HSTR]

    const int tid = threadIdx.x, wid = tid >> 5, lid = tid & 31;
    const int rq = lid >> 2, cq = lid & 3;
    const int m0 = blockIdx.y * 128, n0 = blockIdx.x * 128;
    const int m_warp = (wid >> 2) * 64;
    const int n_warp = (wid & 3) * 32;

    const uint32_t sA = smem_u32(As), sB = smem_u32(Bs);

    float acc[4][4][4];
#pragma unroll
    for (int i = 0; i < 4; i++)
#pragma unroll
        for (int j = 0; j < 4; j++)
#pragma unroll
            for (int q = 0; q < 4; q++) acc[i][j][q] = 0.f;

    auto load_stage = [&](int c, int s) {
        const int k0 = c * 64;
#pragma unroll
        for (int i = 0; i < 4; i++) {
            int ch = tid + i * 256;
            int row = ch >> 3, c16 = ch & 7;
            uint32_t so = (uint32_t)((s * ABUF + row * HSTR + c16 * 8) * 2);
            cp_async16(sA + so, A + (size_t)(m0 + row) * KDIM + k0 + c16 * 8);
            cp_async16(sB + so, Bt + (size_t)(n0 + row) * KDIM + k0 + c16 * 8);
        }
        asm volatile("cp.async.commit_group;" ::: "memory");
    };

    load_stage(0, 0);
    load_stage(1, 1);

#pragma unroll 1
    for (int c = 0; c < NCH; c++) {
        if (c + 1 < NCH) asm volatile("cp.async.wait_group 1;" ::: "memory");
        else             asm volatile("cp.async.wait_group 0;" ::: "memory");
        __syncthreads();
        if (c + 2 < NCH) load_stage(c + 2, (c + 2) % 3);

        const __half* Ab = As + (c % 3) * ABUF;
        const __half* Bb = Bs + (c % 3) * ABUF;
#pragma unroll
        for (int ks = 0; ks < 4; ks++) {
            const int kl = ks * 16 + 2 * cq;
            uint32_t af[4][4], bf[4][2];
#pragma unroll
            for (int mt = 0; mt < 4; mt++) {
                const __half* p = Ab + (m_warp + mt * 16 + rq) * HSTR + kl;
                af[mt][0] = *(const uint32_t*)p;
                af[mt][1] = *(const uint32_t*)(p + 8 * HSTR);
                af[mt][2] = *(const uint32_t*)(p + 8);
                af[mt][3] = *(const uint32_t*)(p + 8 * HSTR + 8);
            }
#pragma unroll
            for (int nt = 0; nt < 4; nt++) {
                const __half* p = Bb + (n_warp + nt * 8 + rq) * HSTR + kl;
                bf[nt][0] = *(const uint32_t*)p;
                bf[nt][1] = *(const uint32_t*)(p + 8);
            }
#pragma unroll
            for (int mt = 0; mt < 4; mt++)
#pragma unroll
                for (int nt = 0; nt < 4; nt++)
                    mma_f16(acc[mt][nt], af[mt], bf[nt]);
        }
    }
    __syncthreads();

#pragma unroll
    for (int mt = 0; mt < 4; mt++) {
        int r0 = m0 + m_warp + mt * 16 + rq;
#pragma unroll
        for (int nt = 0; nt < 4; nt++) {
            int cb = n0 + n_warp + nt * 8 + 2 * cq;
            float2 bz = *(const float2*)(bias + cb);
            float o00 = acc[mt][nt][0] + bz.x, o01 = acc[mt][nt][1] + bz.y;
            float o10 = acc[mt][nt][2] + bz.x, o11 = acc[mt][nt][3] + bz.y;
            if (HALF_OUT) {
                __half* C = (__half*)Cv;
                *(uint32_t*)(C + (size_t)r0 * N + cb)       = packh2(o00, o01);
                *(uint32_t*)(C + (size_t)(r0 + 8) * N + cb) = packh2(o10, o11);
            } else {
                float* C = (float*)Cv;
                *(float2*)(C + (size_t)r0 * N + cb)       = make_float2(o00, o01);
                *(float2*)(C + (size_t)(r0 + 8) * N + cb) = make_float2(o10, o11);
            }
        }
    }
}

// ---------------- fp16 mma flash attention ----------------------------------
// CTA: 128 queries, 4 warps (32 rows each). 64-key double-buffered K/V.
// Fragments via ldmatrix (x4 / x4.trans). PV A-fragments come straight from
// the S accumulator layout (no shuffles). smem stride 72 halfs.
#define AQ_F (128 * HSTR)
#define AS_F (64 * HSTR)
#define ATT_SMEM ((AQ_F + 4 * AS_F) * 2)   // 55296 bytes

__global__ __launch_bounds__(128) void attn_f16_kernel(
    const __half* __restrict__ qkv, __half* __restrict__ out)
{
    extern __shared__ __half smh[];
    __half* Qs  = smh;                     // [128][HSTR]
    __half* Kb0 = smh + AQ_F;              // [2][64][HSTR]
    __half* Vb0 = smh + AQ_F + 2 * AS_F;   // [2][64][HSTR]

    const int tid = threadIdx.x, wid = tid >> 5, lid = tid & 31;
    const int rq = lid >> 2, cq = lid & 3;
    const int b = blockIdx.z, h = blockIdx.y;
    const int bx = (int)gridDim.x - 1 - (int)blockIdx.x;   // heavy blocks first
    const int q0 = bx * 128;
    const __half* base = qkv + (size_t)b * TSEQ * QKV_N + h * DHEAD;

    const uint32_t sQ = smem_u32(Qs), sK = smem_u32(Kb0), sV = smem_u32(Vb0);

    // ldmatrix lane-address components
    const int l7 = lid & 7, lb3 = (lid >> 3) & 1, lb4 = lid >> 4;

    // Q tile: 128 rows x 8 16B-chunks
#pragma unroll
    for (int i = 0; i < 8; i++) {
        int ch = tid + i * 128;
        int r = ch >> 3, c16 = ch & 7;
        cp_async16(sQ + (uint32_t)((r * HSTR + c16 * 8) * 2),
                   base + (size_t)(q0 + r) * QKV_N + c16 * 8);
    }
    asm volatile("cp.async.commit_group;" ::: "memory");

    auto load_sub = [&](int st) {
        const int buf = st & 1;
#pragma unroll
        for (int i = 0; i < 4; i++) {
            int ch = tid + i * 128;
            int r = ch >> 3, c16 = ch & 7;
            const __half* g = base + (size_t)(st * 64 + r) * QKV_N + c16 * 8;
            uint32_t so = (uint32_t)((buf * AS_F + r * HSTR + c16 * 8) * 2);
            cp_async16(sK + so, g + DMODEL);
            cp_async16(sV + so, g + 2 * DMODEL);
        }
        asm volatile("cp.async.commit_group;" ::: "memory");
    };

    float acc[2][8][4];
#pragma unroll
    for (int mt = 0; mt < 2; mt++)
#pragma unroll
        for (int nt = 0; nt < 8; nt++)
#pragma unroll
            for (int j = 0; j < 4; j++) acc[mt][nt][j] = 0.f;
    float mrow[2][2], lrow[2][2];
#pragma unroll
    for (int mt = 0; mt < 2; mt++) {
        mrow[mt][0] = -1e30f; mrow[mt][1] = -1e30f;
        lrow[mt][0] = 0.f;    lrow[mt][1] = 0.f;
    }

    const int mrow0 = wid * 32;
    const float SC = 0.1803368801111f;   // (1/8) * log2(e)

    load_sub(0);

    const int nst = 2 * bx + 2;
#pragma unroll 1
    for (int st = 0; st < nst; st++) {
        if (st + 1 < nst) {
            load_sub(st + 1);
            asm volatile("cp.async.wait_group 1;" ::: "memory");
        } else {
            asm volatile("cp.async.wait_group 0;" ::: "memory");
        }
        __syncthreads();

        const uint32_t sKb = sK + (uint32_t)((st & 1) * AS_F * 2);
        const uint32_t sVb = sV + (uint32_t)((st & 1) * AS_F * 2);

        // ---- S = Q @ K^T ----
        float s[2][8][4];
#pragma unroll
        for (int mt = 0; mt < 2; mt++)
#pragma unroll
            for (int nt = 0; nt < 8; nt++)
#pragma unroll
                for (int j = 0; j < 4; j++) s[mt][nt][j] = 0.f;

#pragma unroll
        for (int ks = 0; ks < 4; ks++) {
            uint32_t af[2][4];
#pragma unroll
            for (int mt = 0; mt < 2; mt++) {
                uint32_t qa = sQ + (uint32_t)(((mrow0 + mt * 16 + lb3 * 8 + l7) * HSTR
                                   + ks * 16 + lb4 * 8) * 2);
                LDSM4(af[mt][0], af[mt][1], af[mt][2], af[mt][3], qa);
            }
#pragma unroll
            for (int p = 0; p < 4; p++) {
                uint32_t kb[4];
                uint32_t ka = sKb + (uint32_t)(((16 * p + lb4 * 8 + l7) * HSTR
                                   + ks * 16 + lb3 * 8) * 2);
                LDSM4(kb[0], kb[1], kb[2], kb[3], ka);
                mma_f16(s[0][2 * p],     af[0], &kb[0]);
                mma_f16(s[0][2 * p + 1], af[0], &kb[2]);
                mma_f16(s[1][2 * p],     af[1], &kb[0]);
                mma_f16(s[1][2 * p + 1], af[1], &kb[2]);
            }
        }

        // ---- scale, causal mask, online softmax (base-2) ----
        const bool diag = (st >= 2 * bx);
#pragma unroll
        for (int mt = 0; mt < 2; mt++) {
#pragma unroll
            for (int nt = 0; nt < 8; nt++)
#pragma unroll
                for (int j = 0; j < 4; j++) s[mt][nt][j] *= SC;

            if (diag) {
                int row0 = q0 + mrow0 + mt * 16 + rq;
#pragma unroll
                for (int nt = 0; nt < 8; nt++) {
                    int c0 = st * 64 + nt * 8 + 2 * cq;
                    if (c0     > row0)     s[mt][nt][0] = -1e30f;
                    if (c0 + 1 > row0)     s[mt][nt][1] = -1e30f;
                    if (c0     > row0 + 8) s[mt][nt][2] = -1e30f;
                    if (c0 + 1 > row0 + 8) s[mt][nt][3] = -1e30f;
                }
            }

            float mx0 = -1e30f, mx1 = -1e30f;
#pragma unroll
            for (int nt = 0; nt < 8; nt++) {
                mx0 = fmaxf(mx0, fmaxf(s[mt][nt][0], s[mt][nt][1]));
                mx1 = fmaxf(mx1, fmaxf(s[mt][nt][2], s[mt][nt][3]));
            }
            mx0 = fmaxf(mx0, __shfl_xor_sync(0xffffffffu, mx0, 1));
            mx0 = fmaxf(mx0, __shfl_xor_sync(0xffffffffu, mx0, 2));
            mx1 = fmaxf(mx1, __shfl_xor_sync(0xffffffffu, mx1, 1));
            mx1 = fmaxf(mx1, __shfl_xor_sync(0xffffffffu, mx1, 2));

            float mn0 = fmaxf(mrow[mt][0], mx0);
            float mn1 = fmaxf(mrow[mt][1], mx1);
            float sc0 = ex2f(mrow[mt][0] - mn0);
            float sc1 = ex2f(mrow[mt][1] - mn1);
            mrow[mt][0] = mn0; mrow[mt][1] = mn1;
            lrow[mt][0] *= sc0; lrow[mt][1] *= sc1;
#pragma unroll
            for (int nt = 0; nt < 8; nt++) {
                acc[mt][nt][0] *= sc0; acc[mt][nt][1] *= sc0;
                acc[mt][nt][2] *= sc1; acc[mt][nt][3] *= sc1;
            }
            float su0 = 0.f, su1 = 0.f;
#pragma unroll
            for (int nt = 0; nt < 8; nt++) {
                s[mt][nt][0] = ex2f(s[mt][nt][0] - mn0); su0 += s[mt][nt][0];
                s[mt][nt][1] = ex2f(s[mt][nt][1] - mn0); su0 += s[mt][nt][1];
                s[mt][nt][2] = ex2f(s[mt][nt][2] - mn1); su1 += s[mt][nt][2];
                s[mt][nt][3] = ex2f(s[mt][nt][3] - mn1); su1 += s[mt][nt][3];
            }
            su0 += __shfl_xor_sync(0xffffffffu, su0, 1);
            su0 += __shfl_xor_sync(0xffffffffu, su0, 2);
            su1 += __shfl_xor_sync(0xffffffffu, su1, 1);
            su1 += __shfl_xor_sync(0xffffffffu, su1, 2);
            lrow[mt][0] += su0; lrow[mt][1] += su1;
        }

        // ---- O += P @ V  (P fragments: pure register packs from S) ----
#pragma unroll
        for (int kk = 0; kk < 4; kk++) {
            uint32_t pa[2][4];
#pragma unroll
            for (int mt = 0; mt < 2; mt++) {
                pa[mt][0] = packh2(s[mt][2 * kk][0],     s[mt][2 * kk][1]);
                pa[mt][1] = packh2(s[mt][2 * kk][2],     s[mt][2 * kk][3]);
                pa[mt][2] = packh2(s[mt][2 * kk + 1][0], s[mt][2 * kk + 1][1]);
                pa[mt][3] = packh2(s[mt][2 * kk + 1][2], s[mt][2 * kk + 1][3]);
            }
#pragma unroll
            for (int p = 0; p < 4; p++) {
                uint32_t vb[4];
                uint32_t va = sVb + (uint32_t)(((kk * 16 + lb3 * 8 + l7) * HSTR
                                   + p * 16 + lb4 * 8) * 2);
                LDSM4T(vb[0], vb[1], vb[2], vb[3], va);
                mma_f16(acc[0][2 * p],     pa[0], &vb[0]);
                mma_f16(acc[0][2 * p + 1], pa[0], &vb[2]);
                mma_f16(acc[1][2 * p],     pa[1], &vb[0]);
                mma_f16(acc[1][2 * p + 1], pa[1], &vb[2]);
            }
        }
        __syncthreads();   // buffer free for next prefetch
    }

    // ---- epilogue: normalize, fp16 output (feeds proj GEMM) ----
    __half* outp = out + (size_t)b * TSEQ * DMODEL + h * DHEAD;
#pragma unroll
    for (int mt = 0; mt < 2; mt++) {
        float i0 = 1.f / lrow[mt][0], i1 = 1.f / lrow[mt][1];
        int row0 = q0 + mrow0 + mt * 16 + rq;
#pragma unroll
        for (int nt = 0; nt < 8; nt++) {
            int col = nt * 8 + 2 * cq;
            *(uint32_t*)(outp + (size_t)row0 * DMODEL + col) =
                packh2(acc[mt][nt][0] * i0, acc[mt][nt][1] * i0);
            *(uint32_t*)(outp + (size_t)(row0 + 8) * DMODEL + col) =
                packh2(acc[mt][nt][2] * i1, acc[mt][nt][3] * i1);
        }
    }
}

// ---------------------------------------------------------------------------
extern "C" void kernel_launch(void* const* d_in, const int* in_sizes, int n_in,
                              void* d_out, int out_size)
{
    const float* x      = (const float*)d_in[0];   // [2,2048,1024]
    const float* W_attn = (const float*)d_in[1];   // [1024,3072]
    const float* b_attn = (const float*)d_in[2];   // [3072]
    const float* W_proj = (const float*)d_in[3];   // [1024,1024]
    const float* b_proj = (const float*)d_in[4];   // [1024]
    float* out = (float*)d_out;                    // [2,2048,1024]

    __half *qkv, *attn, *xh, *wta, *wtp;
    cudaGetSymbolAddress((void**)&qkv,  g_qkvh);
    cudaGetSymbolAddress((void**)&attn, g_attnh);
    cudaGetSymbolAddress((void**)&xh,   g_xh);
    cudaGetSymbolAddress((void**)&wta,  g_wt_attn);
    cudaGetSymbolAddress((void**)&wtp,  g_wt_proj);

    cudaFuncSetAttribute(gemm_f16_mma<true>,
                         cudaFuncAttributeMaxDynamicSharedMemorySize, GEMM_SMEM);
    cudaFuncSetAttribute(gemm_f16_mma<false>,
                         cudaFuncAttributeMaxDynamicSharedMemorySize, GEMM_SMEM);
    cudaFuncSetAttribute(attn_f16_kernel,
                         cudaFuncAttributeMaxDynamicSharedMemorySize, ATT_SMEM);

    // prep: fp16 conversions (RNE)
    {
        int n4 = BT * DMODEL / 4;
        f2h_kernel<<<(n4 + 255) / 256, 256>>>((const float4*)x, (uint2*)xh, n4);
        transpose_f2h_kernel<<<dim3(QKV_N / 32, KDIM / 32), dim3(32, 8)>>>(W_attn, wta, KDIM, QKV_N);
        transpose_f2h_kernel<<<dim3(DMODEL / 32, KDIM / 32), dim3(32, 8)>>>(W_proj, wtp, KDIM, DMODEL);
    }
    // 1) QKV projection (fp16 mma, fp32 accum, fp16 output)
    gemm_f16_mma<true><<<dim3(QKV_N / 128, BT / 128), 256, GEMM_SMEM>>>(xh, wta, b_attn, qkv, QKV_N);
    // 2) causal flash attention (fp16 mma, fp32 softmax/accum)
    {
        dim3 grid(TSEQ / 128, NHEAD, BATCH);
        attn_f16_kernel<<<grid, 128, ATT_SMEM>>>(qkv, attn);
    }
    // 3) output projection (fp16 mma, fp32 accum, fp32 output)
    gemm_f16_mma<false><<<dim3(DMODEL / 128, BT / 128), 256, GEMM_SMEM>>>(attn, wtp, b_proj, out, DMODEL);
}

// round 7
// speedup vs baseline: 1.8661x; 1.0415x over previous
#include <cuda_runtime.h>
#include <cuda_fp16.h>
#include <cstdint>
#include <math.h>

#define BATCH 2
#define TSEQ  2048
#define DMODEL 1024
#define NHEAD 16
#define DHEAD 64
#define BT (BATCH * TSEQ)          // 4096
#define QKV_N (3 * DMODEL)         // 3072
#define KDIM DMODEL                // K = 1024 for both GEMMs

// ---------------- scratch (device globals; allocation-free rule) ----------
__device__ __align__(256) __half g_qkvh[(size_t)BT * QKV_N];      // [4096,3072]
__device__ __align__(256) __half g_attnh[(size_t)BT * DMODEL];    // [4096,1024]
__device__ __align__(256) __half g_xh[(size_t)BT * DMODEL];       // x in fp16
__device__ __align__(256) __half g_wt_attn[(size_t)QKV_N * KDIM]; // W_attn^T fp16
__device__ __align__(256) __half g_wt_proj[(size_t)DMODEL * KDIM];// W_proj^T fp16

// ---------------- helpers ---------------------------------------------------
__device__ __forceinline__ uint32_t smem_u32(const void* p) {
    uint32_t a;
    asm("{ .reg .u64 t; cvta.to.shared.u64 t, %1; cvt.u32.u64 %0, t; }" : "=r"(a) : "l"(p));
    return a;
}
__device__ __forceinline__ float ex2f(float x) {
    float r;
    asm("ex2.approx.f32 %0, %1;" : "=f"(r) : "f"(x));
    return r;
}
__device__ __forceinline__ void cp_async16(uint32_t saddr, const void* gptr) {
    asm volatile("cp.async.cg.shared.global [%0], [%1], 16;" :: "r"(saddr), "l"(gptr));
}
__device__ __forceinline__ void mma_f16(float* d, const uint32_t* a, const uint32_t* b) {
    asm volatile(
        "mma.sync.aligned.m16n8k16.row.col.f32.f16.f16.f32 "
        "{%0,%1,%2,%3}, {%4,%5,%6,%7}, {%8,%9}, {%0,%1,%2,%3};"
        : "+f"(d[0]), "+f"(d[1]), "+f"(d[2]), "+f"(d[3])
        : "r"(a[0]), "r"(a[1]), "r"(a[2]), "r"(a[3]), "r"(b[0]), "r"(b[1]));
}
#define LDSM4(R0,R1,R2,R3,ADDR) \
  asm volatile("ldmatrix.sync.aligned.m8n8.x4.shared.b16 {%0,%1,%2,%3}, [%4];" \
    : "=r"(R0),"=r"(R1),"=r"(R2),"=r"(R3) : "r"(ADDR))
#define LDSM4T(R0,R1,R2,R3,ADDR) \
  asm volatile("ldmatrix.sync.aligned.m8n8.x4.trans.shared.b16 {%0,%1,%2,%3}, [%4];" \
    : "=r"(R0),"=r"(R1),"=r"(R2),"=r"(R3) : "r"(ADDR))
__device__ __forceinline__ uint32_t packh2(float a, float b) {
    __half2 h = __floats2half2_rn(a, b);
    return *(uint32_t*)&h;
}

// ---------------- prep kernels ---------------------------------------------
__global__ void f2h_kernel(const float4* __restrict__ src,
                           uint2* __restrict__ dst, int n4) {
    int i = blockIdx.x * blockDim.x + threadIdx.x;
    if (i < n4) {
        float4 v = src[i];
        uint2 o;
        o.x = packh2(v.x, v.y);
        o.y = packh2(v.z, v.w);
        dst[i] = o;
    }
}

// Wt[n][k] = half(W[k][n]);  W is [K, N] row-major fp32
__global__ void transpose_f2h_kernel(const float* __restrict__ W,
                                     __half* __restrict__ Wt, int K, int N) {
    __shared__ float tile[32][33];
    int nx = blockIdx.x * 32, kx = blockIdx.y * 32;
    for (int i = threadIdx.y; i < 32; i += 8)
        tile[i][threadIdx.x] = W[(size_t)(kx + i) * N + nx + threadIdx.x];
    __syncthreads();
    for (int i = threadIdx.y; i < 32; i += 8)
        Wt[(size_t)(nx + i) * K + kx + threadIdx.x] = __float2half_rn(tile[threadIdx.x][i]);
}

// ---------------- fp16 mma.sync GEMM (ldmatrix fragments) ------------------
// C[M,N] = A[M,K]h @ Bt[N,K]h^T + bias[N].  CTA 128x128, BK=64, 3 stages.
// smem halfs, stride 72: ldmatrix rows hit banks 4r..4r+3 mod 32 -> conflict-free.
#define HSTR 72
#define ABUF (128 * HSTR)                 // halfs per stage per matrix
#define GEMM_SMEM (6 * ABUF * 2)          // 110592 bytes
#define NCH 16                            // 1024 / 64

template <bool HALF_OUT>
__global__ __launch_bounds__(256, 2) void gemm_f16_mma(
    const __half* __restrict__ A, const __half* __restrict__ Bt,
    const float* __restrict__ bias, void* __restrict__ Cv, int N)
{
    extern __shared__ __half smh[];
    __half* As = smh;                 // [3][128][HSTR]
    __half* Bs = smh + 3 * ABUF;      // [3][128][HSTR]

    const int tid = threadIdx.x, wid = tid >> 5, lid = tid & 31;
    const int rq = lid >> 2, cq = lid & 3;
    const int l7 = lid & 7, lb3 = (lid >> 3) & 1, lb4 = lid >> 4;
    const int m0 = blockIdx.y * 128, n0 = blockIdx.x * 128;
    const int m_warp = (wid >> 2) * 64;
    const int n_warp = (wid & 3) * 32;

    const uint32_t sA = smem_u32(As), sB = smem_u32(Bs);

    float acc[4][4][4];
#pragma unroll
    for (int i = 0; i < 4; i++)
#pragma unroll
        for (int j = 0; j < 4; j++)
#pragma unroll
            for (int q = 0; q < 4; q++) acc[i][j][q] = 0.f;

    auto load_stage = [&](int c, int s) {
        const int k0 = c * 64;
#pragma unroll
        for (int i = 0; i < 4; i++) {
            int ch = tid + i * 256;
            int row = ch >> 3, c16 = ch & 7;
            uint32_t so = (uint32_t)((s * ABUF + row * HSTR + c16 * 8) * 2);
            cp_async16(sA + so, A + (size_t)(m0 + row) * KDIM + k0 + c16 * 8);
            cp_async16(sB + so, Bt + (size_t)(n0 + row) * KDIM + k0 + c16 * 8);
        }
        asm volatile("cp.async.commit_group;" ::: "memory");
    };

    load_stage(0, 0);
    load_stage(1, 1);

#pragma unroll 1
    for (int c = 0; c < NCH; c++) {
        if (c + 1 < NCH) asm volatile("cp.async.wait_group 1;" ::: "memory");
        else             asm volatile("cp.async.wait_group 0;" ::: "memory");
        __syncthreads();
        if (c + 2 < NCH) load_stage(c + 2, (c + 2) % 3);

        const uint32_t sAb = sA + (uint32_t)((c % 3) * ABUF * 2);
        const uint32_t sBb = sB + (uint32_t)((c % 3) * ABUF * 2);
#pragma unroll
        for (int ks = 0; ks < 4; ks++) {
            const int kl = ks * 16;
            uint32_t af[4][4], bf[4][2];
#pragma unroll
            for (int mt = 0; mt < 4; mt++) {
                uint32_t aa = sAb + (uint32_t)(((m_warp + mt * 16 + lb3 * 8 + l7) * HSTR
                                     + kl + lb4 * 8) * 2);
                LDSM4(af[mt][0], af[mt][1], af[mt][2], af[mt][3], aa);
            }
#pragma unroll
            for (int np = 0; np < 2; np++) {
                uint32_t ba = sBb + (uint32_t)(((n_warp + np * 16 + lb4 * 8 + l7) * HSTR
                                     + kl + lb3 * 8) * 2);
                uint32_t b0, b1, b2, b3;
                LDSM4(b0, b1, b2, b3, ba);
                bf[2 * np][0] = b0;     bf[2 * np][1] = b1;
                bf[2 * np + 1][0] = b2; bf[2 * np + 1][1] = b3;
            }
#pragma unroll
            for (int mt = 0; mt < 4; mt++)
#pragma unroll
                for (int nt = 0; nt < 4; nt++)
                    mma_f16(acc[mt][nt], af[mt], bf[nt]);
        }
    }
    __syncthreads();

#pragma unroll
    for (int mt = 0; mt < 4; mt++) {
        int r0 = m0 + m_warp + mt * 16 + rq;
#pragma unroll
        for (int nt = 0; nt < 4; nt++) {
            int cb = n0 + n_warp + nt * 8 + 2 * cq;
            float2 bz = *(const float2*)(bias + cb);
            float o00 = acc[mt][nt][0] + bz.x, o01 = acc[mt][nt][1] + bz.y;
            float o10 = acc[mt][nt][2] + bz.x, o11 = acc[mt][nt][3] + bz.y;
            if (HALF_OUT) {
                __half* C = (__half*)Cv;
                *(uint32_t*)(C + (size_t)r0 * N + cb)       = packh2(o00, o01);
                *(uint32_t*)(C + (size_t)(r0 + 8) * N + cb) = packh2(o10, o11);
            } else {
                float* C = (float*)Cv;
                *(float2*)(C + (size_t)r0 * N + cb)       = make_float2(o00, o01);
                *(float2*)(C + (size_t)(r0 + 8) * N + cb) = make_float2(o10, o11);
            }
        }
    }
}

// ---------------- fp16 mma flash attention (8 warps, 16 rows each) ---------
// CTA: 128 queries, 256 threads. 64-key double-buffered K/V subtiles.
// 2 CTAs/SM -> 512 CTAs = ~1.7 waves; heavy-diagonal-first gives balancing.
#define AQ_F (128 * HSTR)
#define AS_F (64 * HSTR)
#define ATT_SMEM ((AQ_F + 4 * AS_F) * 2)   // 55296 bytes

__global__ __launch_bounds__(256, 2) void attn_f16_kernel(
    const __half* __restrict__ qkv, __half* __restrict__ out)
{
    extern __shared__ __half smh[];
    __half* Qs  = smh;                     // [128][HSTR]

    const int tid = threadIdx.x, wid = tid >> 5, lid = tid & 31;
    const int rq = lid >> 2, cq = lid & 3;
    const int l7 = lid & 7, lb3 = (lid >> 3) & 1, lb4 = lid >> 4;
    const int b = blockIdx.z, h = blockIdx.y;
    const int bx = (int)gridDim.x - 1 - (int)blockIdx.x;   // heavy blocks first
    const int q0 = bx * 128;
    const __half* base = qkv + (size_t)b * TSEQ * QKV_N + h * DHEAD;

    const uint32_t sQ = smem_u32(Qs);
    const uint32_t sK = sQ + AQ_F * 2;
    const uint32_t sV = sK + 2 * AS_F * 2;

    // Q tile: 128 rows x 8 16B-chunks, 256 threads -> 4 iters
#pragma unroll
    for (int i = 0; i < 4; i++) {
        int ch = tid + i * 256;
        int r = ch >> 3, c16 = ch & 7;
        cp_async16(sQ + (uint32_t)((r * HSTR + c16 * 8) * 2),
                   base + (size_t)(q0 + r) * QKV_N + c16 * 8);
    }
    asm volatile("cp.async.commit_group;" ::: "memory");

    auto load_sub = [&](int st) {
        const int buf = st & 1;
#pragma unroll
        for (int i = 0; i < 2; i++) {
            int ch = tid + i * 256;
            int r = ch >> 3, c16 = ch & 7;
            const __half* g = base + (size_t)(st * 64 + r) * QKV_N + c16 * 8;
            uint32_t so = (uint32_t)((buf * AS_F + r * HSTR + c16 * 8) * 2);
            cp_async16(sK + so, g + DMODEL);
            cp_async16(sV + so, g + 2 * DMODEL);
        }
        asm volatile("cp.async.commit_group;" ::: "memory");
    };

    float acc[8][4];
#pragma unroll
    for (int nt = 0; nt < 8; nt++)
#pragma unroll
        for (int j = 0; j < 4; j++) acc[nt][j] = 0.f;
    float mrow[2] = {-1e30f, -1e30f}, lrow[2] = {0.f, 0.f};

    const int mrow0 = wid * 16;          // 8 warps x 16 rows
    const float SC = 0.1803368801111f;   // (1/8) * log2(e)

    load_sub(0);

    const int nst = 2 * bx + 2;
#pragma unroll 1
    for (int st = 0; st < nst; st++) {
        if (st + 1 < nst) {
            load_sub(st + 1);
            asm volatile("cp.async.wait_group 1;" ::: "memory");
        } else {
            asm volatile("cp.async.wait_group 0;" ::: "memory");
        }
        __syncthreads();

        const uint32_t sKb = sK + (uint32_t)((st & 1) * AS_F * 2);
        const uint32_t sVb = sV + (uint32_t)((st & 1) * AS_F * 2);

        // ---- S = Q @ K^T ----
        float s[8][4];
#pragma unroll
        for (int nt = 0; nt < 8; nt++)
#pragma unroll
            for (int j = 0; j < 4; j++) s[nt][j] = 0.f;

#pragma unroll
        for (int ks = 0; ks < 4; ks++) {
            uint32_t af[4];
            uint32_t qa = sQ + (uint32_t)(((mrow0 + lb3 * 8 + l7) * HSTR
                               + ks * 16 + lb4 * 8) * 2);
            LDSM4(af[0], af[1], af[2], af[3], qa);
#pragma unroll
            for (int p = 0; p < 4; p++) {
                uint32_t kb[4];
                uint32_t ka = sKb + (uint32_t)(((16 * p + lb4 * 8 + l7) * HSTR
                                   + ks * 16 + lb3 * 8) * 2);
                LDSM4(kb[0], kb[1], kb[2], kb[3], ka);
                mma_f16(s[2 * p],     af, &kb[0]);
                mma_f16(s[2 * p + 1], af, &kb[2]);
            }
        }

        // ---- scale, causal mask, online softmax (base-2) ----
        const bool diag = (st >= 2 * bx);
#pragma unroll
        for (int nt = 0; nt < 8; nt++)
#pragma unroll
            for (int j = 0; j < 4; j++) s[nt][j] *= SC;

        if (diag) {
            int row0 = q0 + mrow0 + rq;
#pragma unroll
            for (int nt = 0; nt < 8; nt++) {
                int c0 = st * 64 + nt * 8 + 2 * cq;
                if (c0     > row0)     s[nt][0] = -1e30f;
                if (c0 + 1 > row0)     s[nt][1] = -1e30f;
                if (c0     > row0 + 8) s[nt][2] = -1e30f;
                if (c0 + 1 > row0 + 8) s[nt][3] = -1e30f;
            }
        }

        float mx0 = -1e30f, mx1 = -1e30f;
#pragma unroll
        for (int nt = 0; nt < 8; nt++) {
            mx0 = fmaxf(mx0, fmaxf(s[nt][0], s[nt][1]));
            mx1 = fmaxf(mx1, fmaxf(s[nt][2], s[nt][3]));
        }
        mx0 = fmaxf(mx0, __shfl_xor_sync(0xffffffffu, mx0, 1));
        mx0 = fmaxf(mx0, __shfl_xor_sync(0xffffffffu, mx0, 2));
        mx1 = fmaxf(mx1, __shfl_xor_sync(0xffffffffu, mx1, 1));
        mx1 = fmaxf(mx1, __shfl_xor_sync(0xffffffffu, mx1, 2));

        float mn0 = fmaxf(mrow[0], mx0);
        float mn1 = fmaxf(mrow[1], mx1);
        float sc0 = ex2f(mrow[0] - mn0);
        float sc1 = ex2f(mrow[1] - mn1);
        mrow[0] = mn0; mrow[1] = mn1;
        lrow[0] *= sc0; lrow[1] *= sc1;
#pragma unroll
        for (int nt = 0; nt < 8; nt++) {
            acc[nt][0] *= sc0; acc[nt][1] *= sc0;
            acc[nt][2] *= sc1; acc[nt][3] *= sc1;
        }
        float su0 = 0.f, su1 = 0.f;
#pragma unroll
        for (int nt = 0; nt < 8; nt++) {
            s[nt][0] = ex2f(s[nt][0] - mn0); su0 += s[nt][0];
            s[nt][1] = ex2f(s[nt][1] - mn0); su0 += s[nt][1];
            s[nt][2] = ex2f(s[nt][2] - mn1); su1 += s[nt][2];
            s[nt][3] = ex2f(s[nt][3] - mn1); su1 += s[nt][3];
        }
        su0 += __shfl_xor_sync(0xffffffffu, su0, 1);
        su0 += __shfl_xor_sync(0xffffffffu, su0, 2);
        su1 += __shfl_xor_sync(0xffffffffu, su1, 1);
        su1 += __shfl_xor_sync(0xffffffffu, su1, 2);
        lrow[0] += su0; lrow[1] += su1;

        // ---- O += P @ V  (P fragments: register packs from S) ----
#pragma unroll
        for (int kk = 0; kk < 4; kk++) {
            uint32_t pa[4];
            pa[0] = packh2(s[2 * kk][0],     s[2 * kk][1]);
            pa[1] = packh2(s[2 * kk][2],     s[2 * kk][3]);
            pa[2] = packh2(s[2 * kk + 1][0], s[2 * kk + 1][1]);
            pa[3] = packh2(s[2 * kk + 1][2], s[2 * kk + 1][3]);
#pragma unroll
            for (int p = 0; p < 4; p++) {
                uint32_t vb[4];
                uint32_t va = sVb + (uint32_t)(((kk * 16 + lb3 * 8 + l7) * HSTR
                                   + p * 16 + lb4 * 8) * 2);
                LDSM4T(vb[0], vb[1], vb[2], vb[3], va);
                mma_f16(acc[2 * p],     pa, &vb[0]);
                mma_f16(acc[2 * p + 1], pa, &vb[2]);
            }
        }
        __syncthreads();   // buffer free for next prefetch
    }

    // ---- epilogue: normalize, fp16 output (feeds proj GEMM) ----
    __half* outp = out + (size_t)b * TSEQ * DMODEL + h * DHEAD;
    float i0 = 1.f / lrow[0], i1 = 1.f / lrow[1];
    int row0 = q0 + mrow0 + rq;
#pragma unroll
    for (int nt = 0; nt < 8; nt++) {
        int col = nt * 8 + 2 * cq;
        *(uint32_t*)(outp + (size_t)row0 * DMODEL + col) =
            packh2(acc[nt][0] * i0, acc[nt][1] * i0);
        *(uint32_t*)(outp + (size_t)(row0 + 8) * DMODEL + col) =
            packh2(acc[nt][2] * i1, acc[nt][3] * i1);
    }
}

// ---------------------------------------------------------------------------
extern "C" void kernel_launch(void* const* d_in, const int* in_sizes, int n_in,
                              void* d_out, int out_size)
{
    const float* x      = (const float*)d_in[0];   // [2,2048,1024]
    const float* W_attn = (const float*)d_in[1];   // [1024,3072]
    const float* b_attn = (const float*)d_in[2];   // [3072]
    const float* W_proj = (const float*)d_in[3];   // [1024,1024]
    const float* b_proj = (const float*)d_in[4];   // [1024]
    float* out = (float*)d_out;                    // [2,2048,1024]

    __half *qkv, *attn, *xh, *wta, *wtp;
    cudaGetSymbolAddress((void**)&qkv,  g_qkvh);
    cudaGetSymbolAddress((void**)&attn, g_attnh);
    cudaGetSymbolAddress((void**)&xh,   g_xh);
    cudaGetSymbolAddress((void**)&wta,  g_wt_attn);
    cudaGetSymbolAddress((void**)&wtp,  g_wt_proj);

    cudaFuncSetAttribute(gemm_f16_mma<true>,
                         cudaFuncAttributeMaxDynamicSharedMemorySize, GEMM_SMEM);
    cudaFuncSetAttribute(gemm_f16_mma<false>,
                         cudaFuncAttributeMaxDynamicSharedMemorySize, GEMM_SMEM);
    cudaFuncSetAttribute(attn_f16_kernel,
                         cudaFuncAttributeMaxDynamicSharedMemorySize, ATT_SMEM);

    // prep: fp16 conversions (RNE)
    {
        int n4 = BT * DMODEL / 4;
        f2h_kernel<<<(n4 + 255) / 256, 256>>>((const float4*)x, (uint2*)xh, n4);
        transpose_f2h_kernel<<<dim3(QKV_N / 32, KDIM / 32), dim3(32, 8)>>>(W_attn, wta, KDIM, QKV_N);
        transpose_f2h_kernel<<<dim3(DMODEL / 32, KDIM / 32), dim3(32, 8)>>>(W_proj, wtp, KDIM, DMODEL);
    }
    // 1) QKV projection (fp16 mma, fp32 accum, fp16 output)
    gemm_f16_mma<true><<<dim3(QKV_N / 128, BT / 128), 256, GEMM_SMEM>>>(xh, wta, b_attn, qkv, QKV_N);
    // 2) causal flash attention (fp16 mma, fp32 softmax/accum)
    {
        dim3 grid(TSEQ / 128, NHEAD, BATCH);
        attn_f16_kernel<<<grid, 256, ATT_SMEM>>>(qkv, attn);
    }
    // 3) output projection (fp16 mma, fp32 accum, fp32 output)
    gemm_f16_mma<false><<<dim3(DMODEL / 128, BT / 128), 256, GEMM_SMEM>>>(attn, wtp, b_proj, out, DMODEL);
}